// round 2
// baseline (speedup 1.0000x reference)
#include <cuda_runtime.h>

typedef unsigned long long ull;

#define T10 10
#define NT  20
#define NW  3
#define D   128
#define H   8
#define HD  16
#define R   24      // H*NW
#define TPB 256
#define GPB 8       // batches per block (one per warp in phase B)

// ---------------- device scratch ----------------
__device__ __align__(16) float g_QWr[R][D];       // [(h*3+w)][e], scaled 1/sqrt(HD)
__device__ float g_sbias[R];
__device__ __align__(16) float g_queries[NW][D];
// pair-interleaved weights: element (k2, n) = (W[n][2k2], W[n][2k2+1]) over reduction dim k
__device__ __align__(16) float2 g_wv_p[64][128];   // wv:   k = e (token feat), n = c
__device__ __align__(16) float2 g_op_p[64][128];   // outp: k = c,              n = o
__device__ __align__(16) float2 g_fc1_p[64][256];  // fc1:  k = e,              n = j
__device__ __align__(16) float2 g_fc2_p[128][128]; // fc2:  k = j,              n = o

// ---------------- f32x2 helpers ----------------
__device__ __forceinline__ void ffma2(ull& d, ull a, ull b) {
    asm("fma.rn.f32x2 %0, %1, %2, %0;" : "+l"(d) : "l"(a), "l"(b));
}
__device__ __forceinline__ float foldp(ull v) {
    float2 f = *reinterpret_cast<float2*>(&v);
    return f.x + f.y;
}

// ---------------- weight prep ----------------
__global__ void prep_weights(const float* __restrict__ in_proj_w,
                             const float* __restrict__ out_proj_w,
                             const float* __restrict__ fc1_w,
                             const float* __restrict__ fc2_w)
{
    int idx = blockIdx.x * blockDim.x + threadIdx.x;
    int stride = gridDim.x * blockDim.x;
    for (int i = idx; i < 64 * 128; i += stride) {
        int k2 = i >> 7, n = i & 127;
        g_wv_p[k2][n] = make_float2(in_proj_w[(2 * D + n) * D + 2 * k2],
                                    in_proj_w[(2 * D + n) * D + 2 * k2 + 1]);
        g_op_p[k2][n] = make_float2(out_proj_w[n * D + 2 * k2],
                                    out_proj_w[n * D + 2 * k2 + 1]);
    }
    for (int i = idx; i < 64 * 256; i += stride) {
        int k2 = i >> 8, n = i & 255;
        g_fc1_p[k2][n] = make_float2(fc1_w[n * D + 2 * k2], fc1_w[n * D + 2 * k2 + 1]);
    }
    for (int i = idx; i < 128 * 128; i += stride) {
        int k2 = i >> 7, n = i & 127;
        g_fc2_p[k2][n] = make_float2(fc2_w[n * 2 * D + 2 * k2], fc2_w[n * 2 * D + 2 * k2 + 1]);
    }
}

// ---------------- precompute: query LN, q, QW, score bias ----------------
__global__ void precompute_kernel(const float* __restrict__ query_emb,
                                  const float* __restrict__ qg,
                                  const float* __restrict__ qb,
                                  const float* __restrict__ in_proj_w,
                                  const float* __restrict__ in_proj_b)
{
    __shared__ float sq[NW][D];
    __shared__ float qq[NW][D];
    __shared__ float redA[4], redB[4];
    const int tid = threadIdx.x;
    const int lane = tid & 31, warp = tid >> 5;

    for (int w = 0; w < NW; w++) {
        float v = query_emb[w * D + tid];
        float s = v, s2 = v * v;
        #pragma unroll
        for (int o = 16; o; o >>= 1) {
            s  += __shfl_down_sync(0xffffffffu, s,  o);
            s2 += __shfl_down_sync(0xffffffffu, s2, o);
        }
        if (lane == 0) { redA[warp] = s; redB[warp] = s2; }
        __syncthreads();
        float m  = (redA[0] + redA[1] + redA[2] + redA[3]) * (1.0f / D);
        float vv = (redB[0] + redB[1] + redB[2] + redB[3]) * (1.0f / D) - m * m;
        float rs = rsqrtf(vv + 1e-5f);
        sq[w][tid] = (v - m) * rs * qg[tid] + qb[tid];
        __syncthreads();
    }
    for (int w = 0; w < NW; w++) {
        float acc = in_proj_b[tid];
        for (int e = 0; e < D; e++) acc += sq[w][e] * in_proj_w[tid * D + e];
        qq[w][tid] = acc;
        g_queries[w][tid] = sq[w][tid];
    }
    __syncthreads();
    for (int h = 0; h < H; h++)
        for (int w = 0; w < NW; w++) {
            float acc = 0.f;
            #pragma unroll
            for (int d = 0; d < HD; d++)
                acc += qq[w][h * HD + d] * in_proj_w[(D + h * HD + d) * D + tid];
            g_QWr[h * NW + w][tid] = acc * 0.25f;
        }
    if (tid < R) {
        int h = tid / NW, w = tid % NW;
        float acc = 0.f;
        #pragma unroll
        for (int d = 0; d < HD; d++)
            acc += qq[w][h * HD + d] * in_proj_b[D + h * HD + d];
        g_sbias[tid] = acc * 0.25f;
    }
}

// ---------------- fused main kernel ----------------
struct Smem {
    float  tok[2][NT][132];       // 21120
    float2 attn2[2][R][NT];       // 7680 (duplicated attn pairs)
    float  qw[R][D];              // 12288
    float  wt[GPB][R][132];       // 101376 (pad 132 -> head rows on distinct bank pairs)
    float  ctx[GPB][NW][D];       // 12288
    float  x[GPB][NW][D];         // 12288
    float  hbuf[GPB][NW][2 * D];  // 24576
    float  coords[2][NT][2];      // 320
    float  redA[2][NT][4];        // 640
    float  redB[2][NT][4];        // 640
};                                 // total 193216 B

__global__ void __launch_bounds__(TPB, 1) fused_kernel(
    const float* __restrict__ track_left,
    const float* __restrict__ track_right,
    const float* __restrict__ coord_w,
    const float* __restrict__ coord_b,
    const float* __restrict__ pos_emb,
    const float* __restrict__ side_emb,
    const float* __restrict__ tok_g,
    const float* __restrict__ tok_b,
    const float* __restrict__ in_proj_b,
    const float* __restrict__ out_proj_b,
    const float* __restrict__ fc1_b,
    const float* __restrict__ fc2_b,
    const float* __restrict__ pa_g, const float* __restrict__ pa_b,
    const float* __restrict__ pf_g, const float* __restrict__ pf_b,
    const float* __restrict__ head_w, const float* __restrict__ head_b,
    float* __restrict__ out)
{
    extern __shared__ float smem_raw[];
    Smem& S = *reinterpret_cast<Smem*>(smem_raw);
    const int tid  = threadIdx.x;
    const int lane = tid & 31;
    const int warp = tid >> 5;
    const int half = tid >> 7;     // 0/1: which of 2 batches in phase-A pass
    const int f    = tid & 127;    // feature dim
    const int w4   = warp & 3;     // warp index within half

    // stage QW
    for (int i = tid; i < R * D; i += TPB) S.qw[i >> 7][i & 127] = g_QWr[i >> 7][i & 127];

    // hoisted per-feature params
    const float cw0 = coord_w[2 * f], cw1 = coord_w[2 * f + 1];
    const float cb  = coord_b[f];
    const float sd0 = side_emb[f], sd1 = side_emb[D + f];
    const float tg  = tok_g[f],  tbv = tok_b[f];
    float posr[T10];
    #pragma unroll
    for (int t = 0; t < T10; t++) posr[t] = pos_emb[t * D + f];

    // ================= Phase A: tokens / scores / softmax / wt =================
    for (int pass = 0; pass < GPB / 2; pass++) {
        __syncthreads();   // protect tok/attn2/coords reuse
        if (tid < 2 * NT) {
            int hh = tid / NT, t = tid % NT;
            int b = blockIdx.x * GPB + 2 * pass + hh;
            const float* src = (t < T10)
                ? (track_left  + (b * T10 + t) * 2)
                : (track_right + (b * T10 + (t - T10)) * 2);
            S.coords[hh][t][0] = src[0];
            S.coords[hh][t][1] = src[1];
        }
        __syncthreads();

        float pre[NT];
        #pragma unroll
        for (int t = 0; t < NT; t++) {
            float base = cb + posr[(t < T10) ? t : (t - T10)] + ((t < T10) ? sd0 : sd1);
            pre[t] = S.coords[half][t][0] * cw0 + S.coords[half][t][1] * cw1 + base;
        }
        #pragma unroll
        for (int t = 0; t < NT; t++) {
            float s = pre[t], s2 = pre[t] * pre[t];
            #pragma unroll
            for (int o = 16; o; o >>= 1) {
                s  += __shfl_down_sync(0xffffffffu, s,  o);
                s2 += __shfl_down_sync(0xffffffffu, s2, o);
            }
            if (lane == 0) { S.redA[half][t][w4] = s; S.redB[half][t][w4] = s2; }
        }
        __syncthreads();
        #pragma unroll
        for (int t = 0; t < NT; t++) {
            float m  = (S.redA[half][t][0] + S.redA[half][t][1] + S.redA[half][t][2] + S.redA[half][t][3]) * (1.0f / D);
            float vv = (S.redB[half][t][0] + S.redB[half][t][1] + S.redB[half][t][2] + S.redB[half][t][3]) * (1.0f / D) - m * m;
            float rs = rsqrtf(vv + 1e-5f);
            S.tok[half][t][f] = (pre[t] - m) * rs * tg + tbv;
        }
        __syncthreads();

        // scores[r][t] = sbias[r] + QW[r] . tok[t]   (packed over e)
        for (int i = f; i < R * NT; i += 128) {
            int r = i / NT, t = i % NT;
            ull acc = 0;
            #pragma unroll 8
            for (int e4 = 0; e4 < 32; e4++) {
                ulonglong2 q  = *reinterpret_cast<const ulonglong2*>(&S.qw[r][4 * e4]);
                ulonglong2 tt = *reinterpret_cast<const ulonglong2*>(&S.tok[half][t][4 * e4]);
                ffma2(acc, q.x, tt.x);
                ffma2(acc, q.y, tt.y);
            }
            S.attn2[half][r][t].x = foldp(acc) + g_sbias[r];
        }
        __syncthreads();

        // softmax (rows duplicated into float2 for later broadcast-pair loads)
        if (tid < 2 * R) {
            int hh = tid / R, r = tid % R;
            float mx = -1e30f;
            #pragma unroll
            for (int t = 0; t < NT; t++) mx = fmaxf(mx, S.attn2[hh][r][t].x);
            float ex[NT], sum = 0.f;
            #pragma unroll
            for (int t = 0; t < NT; t++) { ex[t] = expf(S.attn2[hh][r][t].x - mx); sum += ex[t]; }
            float inv = 1.0f / sum;
            #pragma unroll
            for (int t = 0; t < NT; t++) {
                float a = ex[t] * inv;
                S.attn2[hh][r][t] = make_float2(a, a);
            }
        }
        __syncthreads();

        // wt[r][:] = attn[r] @ tok  (warp w4 -> rows w4+4j; lane -> 4 e dims)
        {
            const int bp = 2 * pass + half;
            ull acc[6][2] = {};
            #pragma unroll
            for (int t = 0; t < NT; t++) {
                ulonglong2 tp = *reinterpret_cast<const ulonglong2*>(&S.tok[half][t][lane * 4]);
                #pragma unroll
                for (int j = 0; j < 6; j++) {
                    ull a = *reinterpret_cast<const ull*>(&S.attn2[half][w4 + 4 * j][t]);
                    ffma2(acc[j][0], a, tp.x);
                    ffma2(acc[j][1], a, tp.y);
                }
            }
            #pragma unroll
            for (int j = 0; j < 6; j++) {
                ulonglong2 v; v.x = acc[j][0]; v.y = acc[j][1];
                *reinterpret_cast<ulonglong2*>(&S.wt[bp][w4 + 4 * j][lane * 4]) = v;
            }
        }
    }
    __syncthreads();   // wt complete for all 8 batches

    // ================= Phase B: warp-per-batch =================
    const int g  = warp;
    const int b  = blockIdx.x * GPB + g;
    const int c0 = lane * 4;
    const int h3 = (lane >> 2) * 3;   // head base row in wt

    float xreg[NW][4];

    // -------- ctx = wt @ wv + bv --------
    {
        ull acc[NW][4] = {};
        #pragma unroll 4
        for (int e2 = 0; e2 < 64; e2++) {
            ulonglong2 w01 = *reinterpret_cast<const ulonglong2*>(&g_wv_p[e2][c0]);
            ulonglong2 w23 = *reinterpret_cast<const ulonglong2*>(&g_wv_p[e2][c0 + 2]);
            ull a0 = *reinterpret_cast<const ull*>(&S.wt[g][h3 + 0][2 * e2]);
            ull a1 = *reinterpret_cast<const ull*>(&S.wt[g][h3 + 1][2 * e2]);
            ull a2 = *reinterpret_cast<const ull*>(&S.wt[g][h3 + 2][2 * e2]);
            ffma2(acc[0][0], a0, w01.x); ffma2(acc[0][1], a0, w01.y);
            ffma2(acc[0][2], a0, w23.x); ffma2(acc[0][3], a0, w23.y);
            ffma2(acc[1][0], a1, w01.x); ffma2(acc[1][1], a1, w01.y);
            ffma2(acc[1][2], a1, w23.x); ffma2(acc[1][3], a1, w23.y);
            ffma2(acc[2][0], a2, w01.x); ffma2(acc[2][1], a2, w01.y);
            ffma2(acc[2][2], a2, w23.x); ffma2(acc[2][3], a2, w23.y);
        }
        float4 bias = *reinterpret_cast<const float4*>(&in_proj_b[2 * D + c0]);
        #pragma unroll
        for (int w = 0; w < NW; w++) {
            float4 v = make_float4(foldp(acc[w][0]) + bias.x, foldp(acc[w][1]) + bias.y,
                                   foldp(acc[w][2]) + bias.z, foldp(acc[w][3]) + bias.w);
            *reinterpret_cast<float4*>(&S.ctx[g][w][c0]) = v;
        }
    }
    __syncthreads();

    // -------- attn_out = ctx @ outp + b; x = LN(queries + attn_out) --------
    {
        ull acc[NW][4] = {};
        #pragma unroll 4
        for (int c2 = 0; c2 < 64; c2++) {
            ulonglong2 w01 = *reinterpret_cast<const ulonglong2*>(&g_op_p[c2][c0]);
            ulonglong2 w23 = *reinterpret_cast<const ulonglong2*>(&g_op_p[c2][c0 + 2]);
            #pragma unroll
            for (int w = 0; w < NW; w++) {
                ull a = *reinterpret_cast<const ull*>(&S.ctx[g][w][2 * c2]);
                ffma2(acc[w][0], a, w01.x); ffma2(acc[w][1], a, w01.y);
                ffma2(acc[w][2], a, w23.x); ffma2(acc[w][3], a, w23.y);
            }
        }
        float4 ob = *reinterpret_cast<const float4*>(&out_proj_b[c0]);
        float4 gg = *reinterpret_cast<const float4*>(&pa_g[c0]);
        float4 bb = *reinterpret_cast<const float4*>(&pa_b[c0]);
        #pragma unroll
        for (int w = 0; w < NW; w++) {
            float4 q4 = *reinterpret_cast<const float4*>(&g_queries[w][c0]);
            float val[4];
            val[0] = foldp(acc[w][0]) + ob.x + q4.x;
            val[1] = foldp(acc[w][1]) + ob.y + q4.y;
            val[2] = foldp(acc[w][2]) + ob.z + q4.z;
            val[3] = foldp(acc[w][3]) + ob.w + q4.w;
            float s  = val[0] + val[1] + val[2] + val[3];
            float s2 = val[0]*val[0] + val[1]*val[1] + val[2]*val[2] + val[3]*val[3];
            #pragma unroll
            for (int o = 16; o; o >>= 1) {
                s  += __shfl_xor_sync(0xffffffffu, s,  o);
                s2 += __shfl_xor_sync(0xffffffffu, s2, o);
            }
            float m  = s * (1.0f / D);
            float vv = s2 * (1.0f / D) - m * m;
            float rs = rsqrtf(vv + 1e-5f);
            xreg[w][0] = (val[0] - m) * rs * gg.x + bb.x;
            xreg[w][1] = (val[1] - m) * rs * gg.y + bb.y;
            xreg[w][2] = (val[2] - m) * rs * gg.z + bb.z;
            xreg[w][3] = (val[3] - m) * rs * gg.w + bb.w;
            *reinterpret_cast<float4*>(&S.x[g][w][c0]) =
                make_float4(xreg[w][0], xreg[w][1], xreg[w][2], xreg[w][3]);
        }
    }
    __syncthreads();

    // -------- fc1 + relu --------
    #pragma unroll
    for (int hh = 0; hh < 2; hh++) {
        ull acc[NW][4] = {};
        #pragma unroll 4
        for (int e2 = 0; e2 < 64; e2++) {
            ulonglong2 w01 = *reinterpret_cast<const ulonglong2*>(&g_fc1_p[e2][hh * D + c0]);
            ulonglong2 w23 = *reinterpret_cast<const ulonglong2*>(&g_fc1_p[e2][hh * D + c0 + 2]);
            #pragma unroll
            for (int w = 0; w < NW; w++) {
                ull a = *reinterpret_cast<const ull*>(&S.x[g][w][2 * e2]);
                ffma2(acc[w][0], a, w01.x); ffma2(acc[w][1], a, w01.y);
                ffma2(acc[w][2], a, w23.x); ffma2(acc[w][3], a, w23.y);
            }
        }
        float4 fb = *reinterpret_cast<const float4*>(&fc1_b[hh * D + c0]);
        #pragma unroll
        for (int w = 0; w < NW; w++) {
            float4 v = make_float4(fmaxf(foldp(acc[w][0]) + fb.x, 0.f),
                                   fmaxf(foldp(acc[w][1]) + fb.y, 0.f),
                                   fmaxf(foldp(acc[w][2]) + fb.z, 0.f),
                                   fmaxf(foldp(acc[w][3]) + fb.w, 0.f));
            *reinterpret_cast<float4*>(&S.hbuf[g][w][hh * D + c0]) = v;
        }
    }
    __syncthreads();

    // -------- fc2 + residual + LN + head --------
    {
        ull acc[NW][4] = {};
        #pragma unroll 4
        for (int j2 = 0; j2 < 128; j2++) {
            ulonglong2 w01 = *reinterpret_cast<const ulonglong2*>(&g_fc2_p[j2][c0]);
            ulonglong2 w23 = *reinterpret_cast<const ulonglong2*>(&g_fc2_p[j2][c0 + 2]);
            #pragma unroll
            for (int w = 0; w < NW; w++) {
                ull a = *reinterpret_cast<const ull*>(&S.hbuf[g][w][2 * j2]);
                ffma2(acc[w][0], a, w01.x); ffma2(acc[w][1], a, w01.y);
                ffma2(acc[w][2], a, w23.x); ffma2(acc[w][3], a, w23.y);
            }
        }
        float4 fb  = *reinterpret_cast<const float4*>(&fc2_b[c0]);
        float4 gg  = *reinterpret_cast<const float4*>(&pf_g[c0]);
        float4 bb  = *reinterpret_cast<const float4*>(&pf_b[c0]);
        float4 hw0 = *reinterpret_cast<const float4*>(&head_w[c0]);
        float4 hw1 = *reinterpret_cast<const float4*>(&head_w[D + c0]);
        const float hb0 = head_b[0], hb1 = head_b[1];
        #pragma unroll
        for (int w = 0; w < NW; w++) {
            float val[4];
            val[0] = foldp(acc[w][0]) + fb.x + xreg[w][0];
            val[1] = foldp(acc[w][1]) + fb.y + xreg[w][1];
            val[2] = foldp(acc[w][2]) + fb.z + xreg[w][2];
            val[3] = foldp(acc[w][3]) + fb.w + xreg[w][3];
            float s  = val[0] + val[1] + val[2] + val[3];
            float s2 = val[0]*val[0] + val[1]*val[1] + val[2]*val[2] + val[3]*val[3];
            #pragma unroll
            for (int o = 16; o; o >>= 1) {
                s  += __shfl_xor_sync(0xffffffffu, s,  o);
                s2 += __shfl_xor_sync(0xffffffffu, s2, o);
            }
            float m  = s * (1.0f / D);
            float vv = s2 * (1.0f / D) - m * m;
            float rs = rsqrtf(vv + 1e-5f);
            float x2_0 = (val[0] - m) * rs * gg.x + bb.x;
            float x2_1 = (val[1] - m) * rs * gg.y + bb.y;
            float x2_2 = (val[2] - m) * rs * gg.z + bb.z;
            float x2_3 = (val[3] - m) * rs * gg.w + bb.w;
            float d0 = x2_0 * hw0.x + x2_1 * hw0.y + x2_2 * hw0.z + x2_3 * hw0.w;
            float d1 = x2_0 * hw1.x + x2_1 * hw1.y + x2_2 * hw1.z + x2_3 * hw1.w;
            #pragma unroll
            for (int o = 16; o; o >>= 1) {
                d0 += __shfl_xor_sync(0xffffffffu, d0, o);
                d1 += __shfl_xor_sync(0xffffffffu, d1, o);
            }
            if (lane == 0) {
                out[b * 6 + w * 2 + 0] = d0 + hb0;
                out[b * 6 + w * 2 + 1] = d1 + hb1;
            }
        }
    }
}

// ---------------- launch ----------------
extern "C" void kernel_launch(void* const* d_in, const int* in_sizes, int n_in,
                              void* d_out, int out_size)
{
    const float* track_left   = (const float*)d_in[0];
    const float* track_right  = (const float*)d_in[1];
    const float* coord_w      = (const float*)d_in[2];
    const float* coord_b      = (const float*)d_in[3];
    const float* pos_emb      = (const float*)d_in[4];
    const float* side_emb     = (const float*)d_in[5];
    const float* query_emb    = (const float*)d_in[6];
    const float* tokens_ln_g  = (const float*)d_in[7];
    const float* tokens_ln_b  = (const float*)d_in[8];
    const float* queries_ln_g = (const float*)d_in[9];
    const float* queries_ln_b = (const float*)d_in[10];
    const float* in_proj_w    = (const float*)d_in[11];
    const float* in_proj_b    = (const float*)d_in[12];
    const float* out_proj_w   = (const float*)d_in[13];
    const float* out_proj_b   = (const float*)d_in[14];
    const float* fc1_w        = (const float*)d_in[15];
    const float* fc1_b        = (const float*)d_in[16];
    const float* fc2_w        = (const float*)d_in[17];
    const float* fc2_b        = (const float*)d_in[18];
    const float* pa_g         = (const float*)d_in[19];
    const float* pa_b         = (const float*)d_in[20];
    const float* pf_g         = (const float*)d_in[21];
    const float* pf_b         = (const float*)d_in[22];
    const float* head_w       = (const float*)d_in[23];
    const float* head_b       = (const float*)d_in[24];
    float* out = (float*)d_out;

    const int nb = in_sizes[0] / (T10 * 2);   // 32768

    prep_weights<<<96, 256>>>(in_proj_w, out_proj_w, fc1_w, fc2_w);
    precompute_kernel<<<1, 128>>>(query_emb, queries_ln_g, queries_ln_b, in_proj_w, in_proj_b);

    cudaFuncSetAttribute(fused_kernel, cudaFuncAttributeMaxDynamicSharedMemorySize,
                         (int)sizeof(Smem));

    fused_kernel<<<nb / GPB, TPB, sizeof(Smem)>>>(
        track_left, track_right, coord_w, coord_b, pos_emb, side_emb,
        tokens_ln_g, tokens_ln_b, in_proj_b, out_proj_b, fc1_b, fc2_b,
        pa_g, pa_b, pf_g, pf_b, head_w, head_b, out);
}

// round 3
// speedup vs baseline: 1.1766x; 1.1766x over previous
#include <cuda_runtime.h>

typedef unsigned long long ull;

#define T10 10
#define NT  20
#define NW  3
#define D   128
#define H   8
#define HD  16
#define R   24      // H*NW
#define TPB 128
#define GPB 2       // batches per block

// ---------------- device scratch ----------------
__device__ __align__(16) float g_QWr[R][D];       // [(h*3+w)][e], scaled 1/sqrt(HD)
__device__ float g_sbias[R];
__device__ __align__(16) float g_queries[NW][D];
// pair-interleaved weights: element (k2, n) = (W[n][2k2], W[n][2k2+1]) over reduction dim k
__device__ __align__(16) float2 g_wv_p[64][128];   // k = e (token feat), n = c
__device__ __align__(16) float2 g_op_p[64][128];   // k = c,              n = o
__device__ __align__(16) float2 g_fc1_p[64][256];  // k = e,              n = j
__device__ __align__(16) float2 g_fc2_p[128][128]; // k = j,              n = o

// ---------------- f32x2 helpers ----------------
__device__ __forceinline__ void ffma2(ull& d, ull a, ull b) {
    asm("fma.rn.f32x2 %0, %1, %2, %0;" : "+l"(d) : "l"(a), "l"(b));
}
__device__ __forceinline__ float foldp(ull v) {
    float2 f = *reinterpret_cast<float2*>(&v);
    return f.x + f.y;
}

// ---------------- weight prep ----------------
__global__ void prep_weights(const float* __restrict__ in_proj_w,
                             const float* __restrict__ out_proj_w,
                             const float* __restrict__ fc1_w,
                             const float* __restrict__ fc2_w)
{
    int idx = blockIdx.x * blockDim.x + threadIdx.x;
    int stride = gridDim.x * blockDim.x;
    for (int i = idx; i < 64 * 128; i += stride) {
        int k2 = i >> 7, n = i & 127;
        g_wv_p[k2][n] = make_float2(in_proj_w[(2 * D + n) * D + 2 * k2],
                                    in_proj_w[(2 * D + n) * D + 2 * k2 + 1]);
        g_op_p[k2][n] = make_float2(out_proj_w[n * D + 2 * k2],
                                    out_proj_w[n * D + 2 * k2 + 1]);
    }
    for (int i = idx; i < 64 * 256; i += stride) {
        int k2 = i >> 8, n = i & 255;
        g_fc1_p[k2][n] = make_float2(fc1_w[n * D + 2 * k2], fc1_w[n * D + 2 * k2 + 1]);
    }
    for (int i = idx; i < 128 * 128; i += stride) {
        int k2 = i >> 7, n = i & 127;
        g_fc2_p[k2][n] = make_float2(fc2_w[n * 2 * D + 2 * k2], fc2_w[n * 2 * D + 2 * k2 + 1]);
    }
}

// ---------------- precompute: query LN, q, QW, score bias ----------------
__global__ void precompute_kernel(const float* __restrict__ query_emb,
                                  const float* __restrict__ qg,
                                  const float* __restrict__ qb,
                                  const float* __restrict__ in_proj_w,
                                  const float* __restrict__ in_proj_b)
{
    __shared__ float sq[NW][D];
    __shared__ float qq[NW][D];
    __shared__ float redA[4], redB[4];
    const int tid = threadIdx.x;
    const int lane = tid & 31, warp = tid >> 5;

    for (int w = 0; w < NW; w++) {
        float v = query_emb[w * D + tid];
        float s = v, s2 = v * v;
        #pragma unroll
        for (int o = 16; o; o >>= 1) {
            s  += __shfl_down_sync(0xffffffffu, s,  o);
            s2 += __shfl_down_sync(0xffffffffu, s2, o);
        }
        if (lane == 0) { redA[warp] = s; redB[warp] = s2; }
        __syncthreads();
        float m  = (redA[0] + redA[1] + redA[2] + redA[3]) * (1.0f / D);
        float vv = (redB[0] + redB[1] + redB[2] + redB[3]) * (1.0f / D) - m * m;
        float rs = rsqrtf(vv + 1e-5f);
        sq[w][tid] = (v - m) * rs * qg[tid] + qb[tid];
        __syncthreads();
    }
    for (int w = 0; w < NW; w++) {
        float acc = in_proj_b[tid];
        for (int e = 0; e < D; e++) acc += sq[w][e] * in_proj_w[tid * D + e];
        qq[w][tid] = acc;
        g_queries[w][tid] = sq[w][tid];
    }
    __syncthreads();
    for (int h = 0; h < H; h++)
        for (int w = 0; w < NW; w++) {
            float acc = 0.f;
            #pragma unroll
            for (int d = 0; d < HD; d++)
                acc += qq[w][h * HD + d] * in_proj_w[(D + h * HD + d) * D + tid];
            g_QWr[h * NW + w][tid] = acc * 0.25f;
        }
    if (tid < R) {
        int h = tid / NW, w = tid % NW;
        float acc = 0.f;
        #pragma unroll
        for (int d = 0; d < HD; d++)
            acc += qq[w][h * HD + d] * in_proj_b[D + h * HD + d];
        g_sbias[tid] = acc * 0.25f;
    }
}

// ---------------- fused main kernel ----------------
struct Smem {
    float  tok[NT][132];          // 10560 B (one batch at a time)
    float2 attn2[R][NT];          // 3840  (duplicated pairs)
    float  wt[GPB][R][132];       // 50688
    float  ctx[GPB][NW][D];       // 3072
    float  x[GPB][NW][D];         // 3072
    float  x2[GPB][NW][D];        // 3072
    float  hbuf[GPB][NW][2 * D];  // 6144
    float  part[4 * 6 * D];       // 12288 (cross-warp partials)
    float  coords[NT][2];
    float  redA[96];
    float  redB[96];
};                                 // ~65 KB -> 3 CTAs/SM

__global__ void __launch_bounds__(TPB) fused_kernel(
    const float* __restrict__ track_left,
    const float* __restrict__ track_right,
    const float* __restrict__ coord_w,
    const float* __restrict__ coord_b,
    const float* __restrict__ pos_emb,
    const float* __restrict__ side_emb,
    const float* __restrict__ tok_g,
    const float* __restrict__ tok_b,
    const float* __restrict__ in_proj_b,
    const float* __restrict__ out_proj_b,
    const float* __restrict__ fc1_b,
    const float* __restrict__ fc2_b,
    const float* __restrict__ pa_g, const float* __restrict__ pa_b,
    const float* __restrict__ pf_g, const float* __restrict__ pf_b,
    const float* __restrict__ head_w, const float* __restrict__ head_b,
    float* __restrict__ out)
{
    extern __shared__ float smem_raw[];
    Smem& S = *reinterpret_cast<Smem*>(smem_raw);
    const int tid  = threadIdx.x;
    const int lane = tid & 31;
    const int warp = tid >> 5;

    // hoisted per-feature params (thread == feature dim)
    const float cw0 = coord_w[2 * tid], cw1 = coord_w[2 * tid + 1];
    const float cb  = coord_b[tid];
    const float sd0 = side_emb[tid], sd1 = side_emb[D + tid];
    const float tg  = tok_g[tid],  tbv = tok_b[tid];
    float posr[T10];
    #pragma unroll
    for (int t = 0; t < T10; t++) posr[t] = pos_emb[t * D + tid];

    // ================= Phase A: per batch =================
    for (int g = 0; g < GPB; g++) {
        const int b = blockIdx.x * GPB + g;
        __syncthreads();
        if (tid < NT) {
            const float* src = (tid < T10)
                ? (track_left  + (b * T10 + tid) * 2)
                : (track_right + (b * T10 + (tid - T10)) * 2);
            S.coords[tid][0] = src[0];
            S.coords[tid][1] = src[1];
        }
        __syncthreads();

        float pre[NT];
        #pragma unroll
        for (int t = 0; t < NT; t++) {
            float base = cb + posr[(t < T10) ? t : (t - T10)] + ((t < T10) ? sd0 : sd1);
            pre[t] = S.coords[t][0] * cw0 + S.coords[t][1] * cw1 + base;
        }
        #pragma unroll
        for (int t = 0; t < NT; t++) {
            float s = pre[t], s2 = pre[t] * pre[t];
            #pragma unroll
            for (int o = 16; o; o >>= 1) {
                s  += __shfl_down_sync(0xffffffffu, s,  o);
                s2 += __shfl_down_sync(0xffffffffu, s2, o);
            }
            if (lane == 0) { S.redA[t * 4 + warp] = s; S.redB[t * 4 + warp] = s2; }
        }
        __syncthreads();
        #pragma unroll
        for (int t = 0; t < NT; t++) {
            float m  = (S.redA[t*4] + S.redA[t*4+1] + S.redA[t*4+2] + S.redA[t*4+3]) * (1.0f / D);
            float vv = (S.redB[t*4] + S.redB[t*4+1] + S.redB[t*4+2] + S.redB[t*4+3]) * (1.0f / D) - m * m;
            float rs = rsqrtf(vv + 1e-5f);
            S.tok[t][tid] = (pre[t] - m) * rs * tg + tbv;
        }
        __syncthreads();

        // scores[r][t] = sbias[r] + QW[r] . tok[t]   (QW read from global, L1-resident)
        for (int i = tid; i < R * NT; i += TPB) {
            int r = i / NT, t = i % NT;
            ull acc = 0;
            #pragma unroll 8
            for (int e4 = 0; e4 < 32; e4++) {
                ulonglong2 q  = *reinterpret_cast<const ulonglong2*>(&g_QWr[r][4 * e4]);
                ulonglong2 tt = *reinterpret_cast<const ulonglong2*>(&S.tok[t][4 * e4]);
                ffma2(acc, q.x, tt.x);
                ffma2(acc, q.y, tt.y);
            }
            S.attn2[r][t].x = foldp(acc) + g_sbias[r];
        }
        __syncthreads();

        // softmax over t, write duplicated pairs
        if (tid < R) {
            float mx = -1e30f;
            #pragma unroll
            for (int t = 0; t < NT; t++) mx = fmaxf(mx, S.attn2[tid][t].x);
            float ex[NT], sum = 0.f;
            #pragma unroll
            for (int t = 0; t < NT; t++) { ex[t] = expf(S.attn2[tid][t].x - mx); sum += ex[t]; }
            float inv = 1.0f / sum;
            #pragma unroll
            for (int t = 0; t < NT; t++) {
                float a = ex[t] * inv;
                S.attn2[tid][t] = make_float2(a, a);
            }
        }
        __syncthreads();

        // wt[r][:] = attn[r] @ tok  (warp -> rows warp+4j, lane -> 4 dims)
        {
            ull acc[6][2] = {};
            #pragma unroll
            for (int t = 0; t < NT; t++) {
                ulonglong2 tp = *reinterpret_cast<const ulonglong2*>(&S.tok[t][lane * 4]);
                #pragma unroll
                for (int j = 0; j < 6; j++) {
                    ull a = *reinterpret_cast<const ull*>(&S.attn2[warp + 4 * j][t]);
                    ffma2(acc[j][0], a, tp.x);
                    ffma2(acc[j][1], a, tp.y);
                }
            }
            #pragma unroll
            for (int j = 0; j < 6; j++) {
                ulonglong2 v; v.x = acc[j][0]; v.y = acc[j][1];
                *reinterpret_cast<ulonglong2*>(&S.wt[g][warp + 4 * j][lane * 4]) = v;
            }
        }
    }
    __syncthreads();   // wt complete for both batches

    // ================= Phase B: cross-warp reduction-split, packed math =================
    const int c0 = lane * 4;
    const int h3 = (lane >> 2) * 3;    // head base row in wt

    // -------- ctx = wt @ wv + bv --------
    {
        ull acc[GPB][NW][4] = {};
        const int k0 = warp * 16;
        #pragma unroll 4
        for (int k2 = k0; k2 < k0 + 16; k2++) {
            ulonglong2 w01 = *reinterpret_cast<const ulonglong2*>(&g_wv_p[k2][c0]);
            ulonglong2 w23 = *reinterpret_cast<const ulonglong2*>(&g_wv_p[k2][c0 + 2]);
            #pragma unroll
            for (int g2 = 0; g2 < GPB; g2++) {
                ull a0 = *reinterpret_cast<const ull*>(&S.wt[g2][h3 + 0][2 * k2]);
                ull a1 = *reinterpret_cast<const ull*>(&S.wt[g2][h3 + 1][2 * k2]);
                ull a2 = *reinterpret_cast<const ull*>(&S.wt[g2][h3 + 2][2 * k2]);
                ffma2(acc[g2][0][0], a0, w01.x); ffma2(acc[g2][0][1], a0, w01.y);
                ffma2(acc[g2][0][2], a0, w23.x); ffma2(acc[g2][0][3], a0, w23.y);
                ffma2(acc[g2][1][0], a1, w01.x); ffma2(acc[g2][1][1], a1, w01.y);
                ffma2(acc[g2][1][2], a1, w23.x); ffma2(acc[g2][1][3], a1, w23.y);
                ffma2(acc[g2][2][0], a2, w01.x); ffma2(acc[g2][2][1], a2, w01.y);
                ffma2(acc[g2][2][2], a2, w23.x); ffma2(acc[g2][2][3], a2, w23.y);
            }
        }
        #pragma unroll
        for (int g2 = 0; g2 < GPB; g2++)
            #pragma unroll
            for (int w = 0; w < NW; w++)
                *reinterpret_cast<float4*>(&S.part[(warp * 6 + g2 * NW + w) * D + c0]) =
                    make_float4(foldp(acc[g2][w][0]), foldp(acc[g2][w][1]),
                                foldp(acc[g2][w][2]), foldp(acc[g2][w][3]));
        __syncthreads();
        #pragma unroll
        for (int r6 = 0; r6 < 6; r6++) {
            float s = S.part[(0*6+r6)*D+tid] + S.part[(1*6+r6)*D+tid]
                    + S.part[(2*6+r6)*D+tid] + S.part[(3*6+r6)*D+tid];
            S.ctx[r6 / 3][r6 % 3][tid] = s + in_proj_b[2 * D + tid];
        }
        __syncthreads();
    }

    // -------- attn_out = ctx @ outp + b; x = LN(queries + attn_out) --------
    {
        ull acc[GPB][NW][4] = {};
        const int k0 = warp * 16;
        #pragma unroll 4
        for (int k2 = k0; k2 < k0 + 16; k2++) {
            ulonglong2 w01 = *reinterpret_cast<const ulonglong2*>(&g_op_p[k2][c0]);
            ulonglong2 w23 = *reinterpret_cast<const ulonglong2*>(&g_op_p[k2][c0 + 2]);
            #pragma unroll
            for (int g2 = 0; g2 < GPB; g2++)
                #pragma unroll
                for (int w = 0; w < NW; w++) {
                    ull a = *reinterpret_cast<const ull*>(&S.ctx[g2][w][2 * k2]);
                    ffma2(acc[g2][w][0], a, w01.x); ffma2(acc[g2][w][1], a, w01.y);
                    ffma2(acc[g2][w][2], a, w23.x); ffma2(acc[g2][w][3], a, w23.y);
                }
        }
        #pragma unroll
        for (int g2 = 0; g2 < GPB; g2++)
            #pragma unroll
            for (int w = 0; w < NW; w++)
                *reinterpret_cast<float4*>(&S.part[(warp * 6 + g2 * NW + w) * D + c0]) =
                    make_float4(foldp(acc[g2][w][0]), foldp(acc[g2][w][1]),
                                foldp(acc[g2][w][2]), foldp(acc[g2][w][3]));
        __syncthreads();
        float val[6];
        #pragma unroll
        for (int r6 = 0; r6 < 6; r6++) {
            float s = S.part[(0*6+r6)*D+tid] + S.part[(1*6+r6)*D+tid]
                    + S.part[(2*6+r6)*D+tid] + S.part[(3*6+r6)*D+tid];
            val[r6] = s + out_proj_b[tid] + g_queries[r6 % 3][tid];
        }
        #pragma unroll
        for (int r6 = 0; r6 < 6; r6++) {
            float s = val[r6], s2 = val[r6] * val[r6];
            #pragma unroll
            for (int o = 16; o; o >>= 1) {
                s  += __shfl_down_sync(0xffffffffu, s,  o);
                s2 += __shfl_down_sync(0xffffffffu, s2, o);
            }
            if (lane == 0) { S.redA[r6 * 4 + warp] = s; S.redB[r6 * 4 + warp] = s2; }
        }
        __syncthreads();
        #pragma unroll
        for (int r6 = 0; r6 < 6; r6++) {
            float m  = (S.redA[r6*4] + S.redA[r6*4+1] + S.redA[r6*4+2] + S.redA[r6*4+3]) * (1.0f / D);
            float vv = (S.redB[r6*4] + S.redB[r6*4+1] + S.redB[r6*4+2] + S.redB[r6*4+3]) * (1.0f / D) - m * m;
            float rs = rsqrtf(vv + 1e-5f);
            S.x[r6 / 3][r6 % 3][tid] = (val[r6] - m) * rs * pa_g[tid] + pa_b[tid];
        }
        __syncthreads();
    }

    // -------- fc1 + relu --------
    #pragma unroll
    for (int hh = 0; hh < 2; hh++) {
        ull acc[GPB][NW][4] = {};
        const int k0 = warp * 16;
        #pragma unroll 4
        for (int k2 = k0; k2 < k0 + 16; k2++) {
            ulonglong2 w01 = *reinterpret_cast<const ulonglong2*>(&g_fc1_p[k2][hh * D + c0]);
            ulonglong2 w23 = *reinterpret_cast<const ulonglong2*>(&g_fc1_p[k2][hh * D + c0 + 2]);
            #pragma unroll
            for (int g2 = 0; g2 < GPB; g2++)
                #pragma unroll
                for (int w = 0; w < NW; w++) {
                    ull a = *reinterpret_cast<const ull*>(&S.x[g2][w][2 * k2]);
                    ffma2(acc[g2][w][0], a, w01.x); ffma2(acc[g2][w][1], a, w01.y);
                    ffma2(acc[g2][w][2], a, w23.x); ffma2(acc[g2][w][3], a, w23.y);
                }
        }
        #pragma unroll
        for (int g2 = 0; g2 < GPB; g2++)
            #pragma unroll
            for (int w = 0; w < NW; w++)
                *reinterpret_cast<float4*>(&S.part[(warp * 6 + g2 * NW + w) * D + c0]) =
                    make_float4(foldp(acc[g2][w][0]), foldp(acc[g2][w][1]),
                                foldp(acc[g2][w][2]), foldp(acc[g2][w][3]));
        __syncthreads();
        #pragma unroll
        for (int r6 = 0; r6 < 6; r6++) {
            float s = S.part[(0*6+r6)*D+tid] + S.part[(1*6+r6)*D+tid]
                    + S.part[(2*6+r6)*D+tid] + S.part[(3*6+r6)*D+tid];
            s += fc1_b[hh * D + tid];
            S.hbuf[r6 / 3][r6 % 3][hh * D + tid] = fmaxf(s, 0.f);
        }
        __syncthreads();
    }

    // -------- fc2 + residual + LN --------
    {
        ull acc[GPB][NW][4] = {};
        const int k0 = warp * 32;
        #pragma unroll 4
        for (int k2 = k0; k2 < k0 + 32; k2++) {
            ulonglong2 w01 = *reinterpret_cast<const ulonglong2*>(&g_fc2_p[k2][c0]);
            ulonglong2 w23 = *reinterpret_cast<const ulonglong2*>(&g_fc2_p[k2][c0 + 2]);
            #pragma unroll
            for (int g2 = 0; g2 < GPB; g2++)
                #pragma unroll
                for (int w = 0; w < NW; w++) {
                    ull a = *reinterpret_cast<const ull*>(&S.hbuf[g2][w][2 * k2]);
                    ffma2(acc[g2][w][0], a, w01.x); ffma2(acc[g2][w][1], a, w01.y);
                    ffma2(acc[g2][w][2], a, w23.x); ffma2(acc[g2][w][3], a, w23.y);
                }
        }
        #pragma unroll
        for (int g2 = 0; g2 < GPB; g2++)
            #pragma unroll
            for (int w = 0; w < NW; w++)
                *reinterpret_cast<float4*>(&S.part[(warp * 6 + g2 * NW + w) * D + c0]) =
                    make_float4(foldp(acc[g2][w][0]), foldp(acc[g2][w][1]),
                                foldp(acc[g2][w][2]), foldp(acc[g2][w][3]));
        __syncthreads();
        float val[6];
        #pragma unroll
        for (int r6 = 0; r6 < 6; r6++) {
            float s = S.part[(0*6+r6)*D+tid] + S.part[(1*6+r6)*D+tid]
                    + S.part[(2*6+r6)*D+tid] + S.part[(3*6+r6)*D+tid];
            val[r6] = s + fc2_b[tid] + S.x[r6 / 3][r6 % 3][tid];
        }
        #pragma unroll
        for (int r6 = 0; r6 < 6; r6++) {
            float s = val[r6], s2 = val[r6] * val[r6];
            #pragma unroll
            for (int o = 16; o; o >>= 1) {
                s  += __shfl_down_sync(0xffffffffu, s,  o);
                s2 += __shfl_down_sync(0xffffffffu, s2, o);
            }
            if (lane == 0) { S.redA[r6 * 4 + warp] = s; S.redB[r6 * 4 + warp] = s2; }
        }
        __syncthreads();
        #pragma unroll
        for (int r6 = 0; r6 < 6; r6++) {
            float m  = (S.redA[r6*4] + S.redA[r6*4+1] + S.redA[r6*4+2] + S.redA[r6*4+3]) * (1.0f / D);
            float vv = (S.redB[r6*4] + S.redB[r6*4+1] + S.redB[r6*4+2] + S.redB[r6*4+3]) * (1.0f / D) - m * m;
            float rs = rsqrtf(vv + 1e-5f);
            S.x2[r6 / 3][r6 % 3][tid] = (val[r6] - m) * rs * pf_g[tid] + pf_b[tid];
        }
        __syncthreads();
    }

    // -------- head --------
    {
        const float hw0 = head_w[tid], hw1 = head_w[D + tid];
        #pragma unroll
        for (int r12 = 0; r12 < 12; r12++) {
            int g2 = r12 / 6, rem = r12 % 6, w = rem >> 1, k = rem & 1;
            float v = S.x2[g2][w][tid] * (k ? hw1 : hw0);
            #pragma unroll
            for (int o = 16; o; o >>= 1) v += __shfl_down_sync(0xffffffffu, v, o);
            if (lane == 0) S.redA[r12 * 4 + warp] = v;
        }
        __syncthreads();
        if (tid < 12) {
            int g2 = tid / 6, rem = tid % 6, k = rem & 1;
            float s = S.redA[tid*4] + S.redA[tid*4+1] + S.redA[tid*4+2] + S.redA[tid*4+3] + head_b[k];
            out[(blockIdx.x * GPB + g2) * 6 + rem] = s;
        }
    }
}

// ---------------- launch ----------------
extern "C" void kernel_launch(void* const* d_in, const int* in_sizes, int n_in,
                              void* d_out, int out_size)
{
    const float* track_left   = (const float*)d_in[0];
    const float* track_right  = (const float*)d_in[1];
    const float* coord_w      = (const float*)d_in[2];
    const float* coord_b      = (const float*)d_in[3];
    const float* pos_emb      = (const float*)d_in[4];
    const float* side_emb     = (const float*)d_in[5];
    const float* query_emb    = (const float*)d_in[6];
    const float* tokens_ln_g  = (const float*)d_in[7];
    const float* tokens_ln_b  = (const float*)d_in[8];
    const float* queries_ln_g = (const float*)d_in[9];
    const float* queries_ln_b = (const float*)d_in[10];
    const float* in_proj_w    = (const float*)d_in[11];
    const float* in_proj_b    = (const float*)d_in[12];
    const float* out_proj_w   = (const float*)d_in[13];
    const float* out_proj_b   = (const float*)d_in[14];
    const float* fc1_w        = (const float*)d_in[15];
    const float* fc1_b        = (const float*)d_in[16];
    const float* fc2_w        = (const float*)d_in[17];
    const float* fc2_b        = (const float*)d_in[18];
    const float* pa_g         = (const float*)d_in[19];
    const float* pa_b         = (const float*)d_in[20];
    const float* pf_g         = (const float*)d_in[21];
    const float* pf_b         = (const float*)d_in[22];
    const float* head_w       = (const float*)d_in[23];
    const float* head_b       = (const float*)d_in[24];
    float* out = (float*)d_out;

    const int nb = in_sizes[0] / (T10 * 2);   // 32768

    prep_weights<<<96, 256>>>(in_proj_w, out_proj_w, fc1_w, fc2_w);
    precompute_kernel<<<1, 128>>>(query_emb, queries_ln_g, queries_ln_b, in_proj_w, in_proj_b);

    cudaFuncSetAttribute(fused_kernel, cudaFuncAttributeMaxDynamicSharedMemorySize,
                         (int)sizeof(Smem));

    fused_kernel<<<nb / GPB, TPB, sizeof(Smem)>>>(
        track_left, track_right, coord_w, coord_b, pos_emb, side_emb,
        tokens_ln_g, tokens_ln_b, in_proj_b, out_proj_b, fc1_b, fc2_b,
        pa_g, pa_b, pf_g, pf_b, head_w, head_b, out);
}